// round 17
// baseline (speedup 1.0000x reference)
#include <cuda_runtime.h>

#define EPS 1e-4f
#define NDIM 512

__device__ __forceinline__ float4 z4f() { return make_float4(0.f, 0.f, 0.f, 0.f); }

// dot of one fp32 row (v0: cols 4L.., v1: 128+4L.., v2: 256+4L.., v3: 384+4L..)
__device__ __forceinline__ float dot_row(float4 v0, float4 v1, float4 v2, float4 v3,
                                         float4 c0, float4 c1, float4 c2, float4 c3) {
    float d0 = 0.f, d1 = 0.f, d2 = 0.f, d3 = 0.f;
    d0 = fmaf(v0.x, c0.x, d0); d1 = fmaf(v0.y, c0.y, d1);
    d2 = fmaf(v0.z, c0.z, d2); d3 = fmaf(v0.w, c0.w, d3);
    d0 = fmaf(v1.x, c1.x, d0); d1 = fmaf(v1.y, c1.y, d1);
    d2 = fmaf(v1.z, c1.z, d2); d3 = fmaf(v1.w, c1.w, d3);
    d0 = fmaf(v2.x, c2.x, d0); d1 = fmaf(v2.y, c2.y, d1);
    d2 = fmaf(v2.z, c2.z, d2); d3 = fmaf(v2.w, c2.w, d3);
    d0 = fmaf(v3.x, c3.x, d0); d1 = fmaf(v3.y, c3.y, d1);
    d2 = fmaf(v3.z, c3.z, d2); d3 = fmaf(v3.w, c3.w, d3);
    return (d0 + d1) + (d2 + d3);
}
__device__ __forceinline__ void acc_row(float4& a0, float4& a1, float4& a2, float4& a3,
                                        float4 v0, float4 v1, float4 v2, float4 v3,
                                        float ri) {
    a0.x = fmaf(ri, v0.x, a0.x); a0.y = fmaf(ri, v0.y, a0.y);
    a0.z = fmaf(ri, v0.z, a0.z); a0.w = fmaf(ri, v0.w, a0.w);
    a1.x = fmaf(ri, v1.x, a1.x); a1.y = fmaf(ri, v1.y, a1.y);
    a1.z = fmaf(ri, v1.z, a1.z); a1.w = fmaf(ri, v1.w, a1.w);
    a2.x = fmaf(ri, v2.x, a2.x); a2.y = fmaf(ri, v2.y, a2.y);
    a2.z = fmaf(ri, v2.z, a2.z); a2.w = fmaf(ri, v2.w, a2.w);
    a3.x = fmaf(ri, v3.x, a3.x); a3.y = fmaf(ri, v3.y, a3.y);
    a3.z = fmaf(ri, v3.z, a3.z); a3.w = fmaf(ri, v3.w, a3.w);
}

__global__ __launch_bounds__(512, 1)
void sinkhorn_kernel(const float* __restrict__ s,
                     const int* __restrict__ nrows,
                     float* __restrict__ out) {
    extern __shared__ __align__(16) float red[];        // 16*512 floats = 32 KB
    __shared__ __align__(16) float c_sh[NDIM];
    __shared__ float ssumA[16];
    __shared__ float ssumB[16];

    const int b    = blockIdx.x;
    const int tid  = threadIdx.x;
    const int lane = tid & 31;
    const int wid  = tid >> 5;                           // 0..15
    const int n    = nrows[b];
    const float* __restrict__ S = s   + (size_t)b * (NDIM * NDIM);
    float* __restrict__       O = out + (size_t)b * (NDIM * NDIM);
    const float4* __restrict__ c4s = (const float4*)c_sh;

    // ===== pass 0: column sums over rows < n (r = 1), MLP-8 load pipeline ======
    {
        const int j4    = (tid & 127) << 2;
        const int slice = tid >> 7;                      // 0..3
        float4 a0 = z4f(), a1 = z4f(), a2 = z4f(), a3 = z4f();
        {
            int i = slice;
            for (; i + 28 < n; i += 32) {
                float4 v0 = *(const float4*)(S + (size_t)(i)      * NDIM + j4);
                float4 v1 = *(const float4*)(S + (size_t)(i + 4)  * NDIM + j4);
                float4 v2 = *(const float4*)(S + (size_t)(i + 8)  * NDIM + j4);
                float4 v3 = *(const float4*)(S + (size_t)(i + 12) * NDIM + j4);
                float4 v4 = *(const float4*)(S + (size_t)(i + 16) * NDIM + j4);
                float4 v5 = *(const float4*)(S + (size_t)(i + 20) * NDIM + j4);
                float4 v6 = *(const float4*)(S + (size_t)(i + 24) * NDIM + j4);
                float4 v7 = *(const float4*)(S + (size_t)(i + 28) * NDIM + j4);
                a0.x += v0.x + v4.x; a0.y += v0.y + v4.y;
                a0.z += v0.z + v4.z; a0.w += v0.w + v4.w;
                a1.x += v1.x + v5.x; a1.y += v1.y + v5.y;
                a1.z += v1.z + v5.z; a1.w += v1.w + v5.w;
                a2.x += v2.x + v6.x; a2.y += v2.y + v6.y;
                a2.z += v2.z + v6.z; a2.w += v2.w + v6.w;
                a3.x += v3.x + v7.x; a3.y += v3.y + v7.y;
                a3.z += v3.z + v7.z; a3.w += v3.w + v7.w;
            }
            for (; i < n; i += 4) {
                float4 v0 = *(const float4*)(S + (size_t)i * NDIM + j4);
                a0.x += v0.x; a0.y += v0.y; a0.z += v0.z; a0.w += v0.w;
            }
            a0.x += a1.x + a2.x + a3.x; a0.y += a1.y + a2.y + a3.y;
            a0.z += a1.z + a2.z + a3.z; a0.w += a1.w + a2.w + a3.w;
        }
        *(float4*)(red + slice * NDIM + j4) = a0;
        __syncthreads();

        float cv = 0.0f;
        {
            float cs = red[tid] + red[NDIM + tid] + red[2 * NDIM + tid] + red[3 * NDIM + tid];
            if (tid < n) cv = __fdividef(1.0f, cs + EPS * (float)n);
            c_sh[tid] = cv;                              // 512 threads = 512 cols
        }
        float v = cv;
        #pragma unroll
        for (int o = 16; o; o >>= 1) v += __shfl_xor_sync(0xffffffffu, v, o);
        if (lane == 0) ssumB[wid] = v;
        __syncthreads();
    }
    float sum_c = 0.0f;
    #pragma unroll
    for (int k = 0; k < 16; ++k) sum_c += ssumB[k];

    // === 4 fused passes: row(2f+1)+col(2f+2); 2-row batch + 2-row lookahead =====
    // branchless full-row loads: cols >= n are masked by c == 0 in the dot, and
    // column partials beyond n are never consumed (c write is guarded by tid < n).
    #pragma unroll 1
    for (int f = 0; f < 4; ++f) {
        const float eps_c = EPS * sum_c;
        float4 acc0 = z4f(), acc1 = z4f(), acc2 = z4f(), acc3 = z4f();
        float rpart = 0.0f;

        const float4 c0 = c4s[lane],      c1 = c4s[lane + 32];
        const float4 c2 = c4s[lane + 64], c3 = c4s[lane + 96];

        int i = wid;
        float4 uA0 = z4f(), uA1 = z4f(), uA2 = z4f(), uA3 = z4f();
        float4 uB0 = z4f(), uB1 = z4f(), uB2 = z4f(), uB3 = z4f();
        if (i < n) {
            const float4* __restrict__ rA = (const float4*)(S + (size_t)i * NDIM);
            uA0 = rA[lane]; uA1 = rA[lane + 32]; uA2 = rA[lane + 64]; uA3 = rA[lane + 96];
        }
        if (i + 16 < n) {
            const float4* __restrict__ rB = (const float4*)(S + (size_t)(i + 16) * NDIM);
            uB0 = rB[lane]; uB1 = rB[lane + 32]; uB2 = rB[lane + 64]; uB3 = rB[lane + 96];
        }
        #pragma unroll 1
        while (i < n) {
            const int inx = i + 32;
            float4 nA0 = z4f(), nA1 = z4f(), nA2 = z4f(), nA3 = z4f();
            float4 nB0 = z4f(), nB1 = z4f(), nB2 = z4f(), nB3 = z4f();
            if (inx < n) {
                const float4* __restrict__ rN = (const float4*)(S + (size_t)inx * NDIM);
                nA0 = rN[lane]; nA1 = rN[lane + 32]; nA2 = rN[lane + 64]; nA3 = rN[lane + 96];
            }
            if (inx + 16 < n) {
                const float4* __restrict__ rN = (const float4*)(S + (size_t)(inx + 16) * NDIM);
                nB0 = rN[lane]; nB1 = rN[lane + 32]; nB2 = rN[lane + 64]; nB3 = rN[lane + 96];
            }

            float tA = dot_row(uA0, uA1, uA2, uA3, c0, c1, c2, c3);
            float tB = dot_row(uB0, uB1, uB2, uB3, c0, c1, c2, c3);
            #pragma unroll
            for (int o = 16; o; o >>= 1) {
                tA += __shfl_xor_sync(0xffffffffu, tA, o);
                tB += __shfl_xor_sync(0xffffffffu, tB, o);
            }
            const float riA = __fdividef(1.0f, tA + eps_c);
            const float riB = __fdividef(1.0f, tB + eps_c);
            rpart += riA;
            acc_row(acc0, acc1, acc2, acc3, uA0, uA1, uA2, uA3, riA);
            if (i + 16 < n) {
                rpart += riB;
                acc_row(acc0, acc1, acc2, acc3, uB0, uB1, uB2, uB3, riB);
            }
            uA0 = nA0; uA1 = nA1; uA2 = nA2; uA3 = nA3;
            uB0 = nB0; uB1 = nB1; uB2 = nB2; uB3 = nB3;
            i = inx;
        }

        float4* __restrict__ rw = (float4*)(red + wid * NDIM);
        rw[lane]      = acc0;
        rw[lane + 32] = acc1;
        rw[lane + 64] = acc2;
        rw[lane + 96] = acc3;
        if (lane == 0) ssumA[wid] = rpart;   // warp-uniform
        __syncthreads();

        float sum_r = 0.0f;
        #pragma unroll
        for (int k = 0; k < 16; ++k) sum_r += ssumA[k];

        float cv = 0.0f;
        {
            float cs = 0.0f;
            #pragma unroll
            for (int w = 0; w < 16; ++w) cs += red[w * NDIM + tid];
            if (tid < n) cv = __fdividef(1.0f, cs + EPS * sum_r);
            c_sh[tid] = cv;
        }
        float v = cv;
        #pragma unroll
        for (int o = 16; o; o >>= 1) v += __shfl_xor_sync(0xffffffffu, v, o);
        if (lane == 0) ssumB[wid] = v;
        __syncthreads();
        sum_c = 0.0f;
        #pragma unroll
        for (int k = 0; k < 16; ++k) sum_c += ssumB[k];
    }

    // === final pass: row step (iter 9) on fp32 S, 2-row batch, fused write =====
    {
        const float eps_c = EPS * sum_c;
        const float4 c0 = c4s[lane],      c1 = c4s[lane + 32];
        const float4 c2 = c4s[lane + 64], c3 = c4s[lane + 96];

        for (int i = wid; i < n; i += 32) {
            const int i2 = i + 16;
            const float4* __restrict__ rA = (const float4*)(S + (size_t)i * NDIM);
            float4 uA0 = rA[lane], uA1 = rA[lane + 32];
            float4 uA2 = rA[lane + 64], uA3 = rA[lane + 96];
            float4 uB0 = z4f(), uB1 = z4f(), uB2 = z4f(), uB3 = z4f();
            if (i2 < n) {
                const float4* __restrict__ rB = (const float4*)(S + (size_t)i2 * NDIM);
                uB0 = rB[lane]; uB1 = rB[lane + 32];
                uB2 = rB[lane + 64]; uB3 = rB[lane + 96];
            }

            float tA = dot_row(uA0, uA1, uA2, uA3, c0, c1, c2, c3);
            float tB = dot_row(uB0, uB1, uB2, uB3, c0, c1, c2, c3);
            #pragma unroll
            for (int o = 16; o; o >>= 1) {
                tA += __shfl_xor_sync(0xffffffffu, tA, o);
                tB += __shfl_xor_sync(0xffffffffu, tB, o);
            }
            const float riA = __fdividef(1.0f, tA + eps_c);
            const float riB = __fdividef(1.0f, tB + eps_c);

            {
                float4* __restrict__ orow = (float4*)(O + (size_t)i * NDIM);
                float4 w;
                w.x = (uA0.x + EPS) * riA * c0.x; w.y = (uA0.y + EPS) * riA * c0.y;
                w.z = (uA0.z + EPS) * riA * c0.z; w.w = (uA0.w + EPS) * riA * c0.w;
                __stcs(orow + lane, w);
                w.x = (uA1.x + EPS) * riA * c1.x; w.y = (uA1.y + EPS) * riA * c1.y;
                w.z = (uA1.z + EPS) * riA * c1.z; w.w = (uA1.w + EPS) * riA * c1.w;
                __stcs(orow + lane + 32, w);
                w.x = (uA2.x + EPS) * riA * c2.x; w.y = (uA2.y + EPS) * riA * c2.y;
                w.z = (uA2.z + EPS) * riA * c2.z; w.w = (uA2.w + EPS) * riA * c2.w;
                __stcs(orow + lane + 64, w);
                w.x = (uA3.x + EPS) * riA * c3.x; w.y = (uA3.y + EPS) * riA * c3.y;
                w.z = (uA3.z + EPS) * riA * c3.z; w.w = (uA3.w + EPS) * riA * c3.w;
                __stcs(orow + lane + 96, w);
            }
            if (i2 < n) {
                float4* __restrict__ orow = (float4*)(O + (size_t)i2 * NDIM);
                float4 w;
                w.x = (uB0.x + EPS) * riB * c0.x; w.y = (uB0.y + EPS) * riB * c0.y;
                w.z = (uB0.z + EPS) * riB * c0.z; w.w = (uB0.w + EPS) * riB * c0.w;
                __stcs(orow + lane, w);
                w.x = (uB1.x + EPS) * riB * c1.x; w.y = (uB1.y + EPS) * riB * c1.y;
                w.z = (uB1.z + EPS) * riB * c1.z; w.w = (uB1.w + EPS) * riB * c1.w;
                __stcs(orow + lane + 32, w);
                w.x = (uB2.x + EPS) * riB * c2.x; w.y = (uB2.y + EPS) * riB * c2.y;
                w.z = (uB2.z + EPS) * riB * c2.z; w.w = (uB2.w + EPS) * riB * c2.w;
                __stcs(orow + lane + 64, w);
                w.x = (uB3.x + EPS) * riB * c3.x; w.y = (uB3.y + EPS) * riB * c3.y;
                w.z = (uB3.z + EPS) * riB * c3.z; w.w = (uB3.w + EPS) * riB * c3.w;
                __stcs(orow + lane + 96, w);
            }
        }
        // zero-fill rows i >= n
        float4* __restrict__ O4 = (float4*)O;
        const float4 z = z4f();
        for (int idx = n * 128 + tid; idx < NDIM * 128; idx += 512)
            __stcs(O4 + idx, z);
    }
}

extern "C" void kernel_launch(void* const* d_in, const int* in_sizes, int n_in,
                              void* d_out, int out_size) {
    const float* s     = (const float*)d_in[0];
    const int*   nrows = (const int*)d_in[1];
    float*       out   = (float*)d_out;
    const int B = in_sizes[1];
    const int shbytes = 16 * NDIM * sizeof(float);   // 32 KB dynamic
    static bool attr_set = false;
    if (!attr_set) {
        cudaFuncSetAttribute(sinkhorn_kernel,
                             cudaFuncAttributeMaxDynamicSharedMemorySize, shbytes);
        attr_set = true;
    }
    sinkhorn_kernel<<<B, 512, shbytes>>>(s, nrows, out);
}